// round 2
// baseline (speedup 1.0000x reference)
#include <cuda_runtime.h>
#include <cstddef>

// Problem constants
constexpr int NB = 32;     // batch
constexpr int NS = 2048;   // sequence
constexpr int ND = 512;    // model dim
constexpr int NF = 512;    // dff
constexpr int C1 = 32;     // s-chunks for pass 1
constexpr int C2 = 32;     // s-chunks for pass 2
constexpr int NW = 8;      // warps per pass block (256 threads)
constexpr int UFC = 4;     // f-chunks in k_u (partials reduced in pass2)
#define INV_SQRT_DFF 0.044194173824159216f  // 1/sqrt(512)

// Scratch (device globals; no allocation anywhere)
__device__ float g_xwp[C1 * NB * ND];   // partial xw per chunk
__device__ float g_xw[NB * ND];
__device__ float g_wsum;
__device__ float g_kwT[NF * NB];        // kw transposed: [f][b]
__device__ float g_cp[64 * NB];         // c partials per f-group of 8
__device__ float g_up[UFC * NB * ND];   // u partials per f-chunk
__device__ float g_xtp[C2 * NB * ND];   // partial xt per chunk
__device__ float g_Tp[C2 * NB];
__device__ float g_T[NB];

// ---------------------------------------------------------------------------
// Pass 1: xw[b,d] = sum_s Wt[s] * x[b,s,d]   (streams 128 MB of x)
// grid (NB, C1), 256 threads
// ---------------------------------------------------------------------------
__global__ __launch_bounds__(256) void k_xw(const float* __restrict__ x,
                                            const float* __restrict__ Wt) {
    const int b = blockIdx.x, c = blockIdx.y;
    const int tid = threadIdx.x, warp = tid >> 5, lane = tid & 31;
    const int rows = NS / C1;  // 64
    const int s0 = c * rows;

    __shared__ float s_wt[NS / C1];
    __shared__ float4 s4[NW * 128];

    if (tid < rows) s_wt[tid] = Wt[s0 + tid];
    __syncthreads();

    float4 acc[4] = {{0,0,0,0},{0,0,0,0},{0,0,0,0},{0,0,0,0}};
#pragma unroll 2
    for (int r = warp; r < rows; r += NW) {
        const float4* xp = (const float4*)x + ((size_t)b * NS + s0 + r) * (ND / 4);
        const float wt = s_wt[r];
#pragma unroll
        for (int j = 0; j < 4; j++) {
            float4 v = xp[32 * j + lane];
            acc[j].x += wt * v.x; acc[j].y += wt * v.y;
            acc[j].z += wt * v.z; acc[j].w += wt * v.w;
        }
    }
#pragma unroll
    for (int j = 0; j < 4; j++) s4[warp * 128 + 32 * j + lane] = acc[j];
    __syncthreads();

    // deterministic cross-warp reduce: thread tid handles d = tid and tid+256
    const float* s = (const float*)s4;
    float v0 = 0.f, v1 = 0.f;
#pragma unroll
    for (int w = 0; w < NW; w++) {
        v0 += s[w * 512 + tid];
        v1 += s[w * 512 + tid + 256];
    }
    float* dst = g_xwp + ((size_t)c * NB + b) * ND;
    dst[tid] = v0;
    dst[tid + 256] = v1;
}

// ---------------------------------------------------------------------------
// Reduce xw partials; block 0 also computes wsum = sum(Wt)
// grid 32, 512 threads
// ---------------------------------------------------------------------------
__global__ __launch_bounds__(512) void k_red1(const float* __restrict__ Wt) {
    const int i = blockIdx.x * 512 + threadIdx.x;
    float v = 0.f;
#pragma unroll
    for (int c = 0; c < C1; c++) v += g_xwp[(size_t)c * NB * ND + i];
    g_xw[i] = v;

    if (blockIdx.x == 0) {
        __shared__ float sr[512];
        float w = 0.f;
        for (int k = threadIdx.x; k < NS; k += 512) w += Wt[k];
        sr[threadIdx.x] = w;
        __syncthreads();
        for (int off = 256; off; off >>= 1) {
            if (threadIdx.x < off) sr[threadIdx.x] += sr[threadIdx.x + off];
            __syncthreads();
        }
        if (threadIdx.x == 0) g_wsum = sr[0];
    }
}

// ---------------------------------------------------------------------------
// kw[b,f] = Wk[f,:].xw[b,:] + bk[f]*wsum    (warp per output, transposed store)
// Also: per-block c partial  c_p[fgroup][b] = sum_{f in group} bq[f]*kw[b,f]
// grid (NB, NF/8), 256 threads
// ---------------------------------------------------------------------------
__global__ __launch_bounds__(256) void k_kw(const float* __restrict__ Wk,
                                            const float* __restrict__ bk,
                                            const float* __restrict__ bq) {
    const int b = blockIdx.x;
    const int warp = threadIdx.x >> 5, lane = threadIdx.x & 31;
    const int f = blockIdx.y * 8 + warp;

    __shared__ float s_c[8];

    const float4* wk = (const float4*)Wk + (size_t)f * (ND / 4);
    const float4* xw = (const float4*)(g_xw + b * ND);
    float dot = 0.f;
#pragma unroll
    for (int q = 0; q < 4; q++) {
        float4 wv = wk[32 * q + lane];
        float4 xv = xw[32 * q + lane];
        dot += wv.x * xv.x + wv.y * xv.y + wv.z * xv.z + wv.w * xv.w;
    }
#pragma unroll
    for (int off = 16; off; off >>= 1) dot += __shfl_xor_sync(0xffffffffu, dot, off);
    if (lane == 0) {
        const float kwv = dot + bk[f] * g_wsum;
        g_kwT[f * NB + b] = kwv;
        s_c[warp] = bq[f] * kwv;
    }
    __syncthreads();
    if (threadIdx.x == 0) {
        float cs = 0.f;
#pragma unroll
        for (int w = 0; w < 8; w++) cs += s_c[w];
        g_cp[blockIdx.y * NB + b] = cs;
    }
}

// ---------------------------------------------------------------------------
// u partial: up[fc][b][d] = sum_{f in chunk} Wq[f,d]*kw[b,f]
// Wq is read EXACTLY ONCE chip-wide. kw chunk for all 32 b lives in smem.
// grid (ND/32 = 16 d-tiles, UFC = 4 f-chunks), 512 threads:
//   dl = tid&31 (d within tile), bg = tid>>5 (16 groups x 2 batches)
// ---------------------------------------------------------------------------
__global__ __launch_bounds__(512) void k_u(const float* __restrict__ Wq) {
    const int d0 = blockIdx.x * 32;
    const int fc = blockIdx.y;
    const int f0 = fc * (NF / UFC);          // 128 f per chunk
    const int tid = threadIdx.x;
    const int dl = tid & 31;
    const int bg = tid >> 5;                 // 0..15

    __shared__ float s_kw[128 * NB];         // [f_local][b], 16 KB

    // cooperative linear copy of kw chunk (contiguous in g_kwT)
    const float4* src = (const float4*)(g_kwT + (size_t)f0 * NB);
    float4* dstS = (float4*)s_kw;
    dstS[tid] = src[tid];
    dstS[tid + 512] = src[tid + 512];
    __syncthreads();

    float2 acc = {0.f, 0.f};
#pragma unroll 8
    for (int f = 0; f < 128; f++) {
        const float w = Wq[(size_t)(f0 + f) * ND + d0 + dl];
        const float2 kv = *(const float2*)&s_kw[f * NB + bg * 2];
        acc.x += w * kv.x;
        acc.y += w * kv.y;
    }
    float* dst = g_up + ((size_t)fc * NB + bg * 2) * ND + d0 + dl;
    dst[0]  = acc.x;
    dst[ND] = acc.y;
}

// ---------------------------------------------------------------------------
// Pass 2: ta[b,s] = (x[b,s].u[b] + c[b])/sqrt(DFF) + bt
//         xt[b,d] += ta*x[b,s,d] ; T[b] += ta      (streams 128 MB of x)
// u and c are reduced from partials in the prologue.
// grid (NB, C2), 256 threads
// ---------------------------------------------------------------------------
__global__ __launch_bounds__(256) void k_pass2(const float* __restrict__ x,
                                               const float* __restrict__ bt) {
    const int b = blockIdx.x, c = blockIdx.y;
    const int tid = threadIdx.x, warp = tid >> 5, lane = tid & 31;
    const int rows = NS / C2;  // 64
    const int s0 = c * rows;

    __shared__ float4 s4[NW * 128];
    __shared__ float s_T[NW];

    // reduce u partials (4 chunks) into registers
    float4 u4[4] = {{0,0,0,0},{0,0,0,0},{0,0,0,0},{0,0,0,0}};
#pragma unroll
    for (int fc = 0; fc < UFC; fc++) {
        const float4* up = (const float4*)(g_up + ((size_t)fc * NB + b) * ND);
#pragma unroll
        for (int j = 0; j < 4; j++) {
            float4 t = up[32 * j + lane];
            u4[j].x += t.x; u4[j].y += t.y; u4[j].z += t.z; u4[j].w += t.w;
        }
    }
    // reduce c partials (64 f-groups) — uniform per block, L1 broadcast
    float cb = 0.f;
#pragma unroll
    for (int g = 0; g < 64; g++) cb += g_cp[g * NB + b];
    const float btv = bt[0];

    float4 acc[4] = {{0,0,0,0},{0,0,0,0},{0,0,0,0},{0,0,0,0}};
    float tsum = 0.f;

#pragma unroll 2
    for (int r = warp; r < rows; r += NW) {
        const float4* xp = (const float4*)x + ((size_t)b * NS + s0 + r) * (ND / 4);
        float4 xv[4];
#pragma unroll
        for (int j = 0; j < 4; j++) xv[j] = xp[32 * j + lane];
        float dot = 0.f;
#pragma unroll
        for (int j = 0; j < 4; j++)
            dot += xv[j].x * u4[j].x + xv[j].y * u4[j].y +
                   xv[j].z * u4[j].z + xv[j].w * u4[j].w;
#pragma unroll
        for (int off = 16; off; off >>= 1) dot += __shfl_xor_sync(0xffffffffu, dot, off);
        const float ta = (dot + cb) * INV_SQRT_DFF + btv;
        tsum += ta;
#pragma unroll
        for (int j = 0; j < 4; j++) {
            acc[j].x += ta * xv[j].x; acc[j].y += ta * xv[j].y;
            acc[j].z += ta * xv[j].z; acc[j].w += ta * xv[j].w;
        }
    }
#pragma unroll
    for (int j = 0; j < 4; j++) s4[warp * 128 + 32 * j + lane] = acc[j];
    if (lane == 0) s_T[warp] = tsum;
    __syncthreads();

    const float* s = (const float*)s4;
    float v0 = 0.f, v1 = 0.f;
#pragma unroll
    for (int w = 0; w < NW; w++) {
        v0 += s[w * 512 + tid];
        v1 += s[w * 512 + tid + 256];
    }
    float* dst = g_xtp + ((size_t)c * NB + b) * ND;
    dst[tid] = v0;
    dst[tid + 256] = v1;
    if (tid == 0) {
        float t = 0.f;
#pragma unroll
        for (int w = 0; w < NW; w++) t += s_T[w];
        g_Tp[c * NB + b] = t;
    }
}

// ---------------------------------------------------------------------------
// Reduce xt partials + T partials. grid 32, 512 threads
// ---------------------------------------------------------------------------
__device__ float g_xt[NB * ND];
__global__ __launch_bounds__(512) void k_red2() {
    const int i = blockIdx.x * 512 + threadIdx.x;
    float v = 0.f;
#pragma unroll
    for (int c = 0; c < C2; c++) v += g_xtp[(size_t)c * NB * ND + i];
    g_xt[i] = v;

    if (blockIdx.x == 0 && threadIdx.x < NB) {
        float t = 0.f;
#pragma unroll
        for (int c = 0; c < C2; c++) t += g_Tp[c * NB + threadIdx.x];
        g_T[threadIdx.x] = t;
    }
}

// ---------------------------------------------------------------------------
// latent[b,f] = Wv[f,:].xt[b,:] + bv[f]*T[b]    (warp per output)
// grid (NB, NF/8), 256 threads
// ---------------------------------------------------------------------------
__global__ __launch_bounds__(256) void k_out(const float* __restrict__ Wv,
                                             const float* __restrict__ bv,
                                             float* __restrict__ out) {
    const int b = blockIdx.x;
    const int warp = threadIdx.x >> 5, lane = threadIdx.x & 31;
    const int f = blockIdx.y * 8 + warp;

    const float4* wv = (const float4*)Wv + (size_t)f * (ND / 4);
    const float4* xt = (const float4*)(g_xt + b * ND);
    float dot = 0.f;
#pragma unroll
    for (int q = 0; q < 4; q++) {
        float4 w = wv[32 * q + lane];
        float4 v = xt[32 * q + lane];
        dot += w.x * v.x + w.y * v.y + w.z * v.z + w.w * v.w;
    }
#pragma unroll
    for (int off = 16; off; off >>= 1) dot += __shfl_xor_sync(0xffffffffu, dot, off);
    if (lane == 0) out[b * NF + f] = dot + bv[f] * g_T[b];
}

// ---------------------------------------------------------------------------
extern "C" void kernel_launch(void* const* d_in, const int* in_sizes, int n_in,
                              void* d_out, int out_size) {
    const float* x  = (const float*)d_in[0];
    const float* Wq = (const float*)d_in[1];
    const float* bq = (const float*)d_in[2];
    const float* Wk = (const float*)d_in[3];
    const float* bk = (const float*)d_in[4];
    const float* Wv = (const float*)d_in[5];
    const float* bv = (const float*)d_in[6];
    const float* Wt = (const float*)d_in[7];
    const float* bt = (const float*)d_in[8];
    float* out = (float*)d_out;

    k_xw   <<<dim3(NB, C1), 256>>>(x, Wt);
    k_red1 <<<32, 512>>>(Wt);
    k_kw   <<<dim3(NB, NF / 8), 256>>>(Wk, bk, bq);
    k_u    <<<dim3(ND / 32, UFC), 512>>>(Wq);
    k_pass2<<<dim3(NB, C2), 256>>>(x, bt);
    k_red2 <<<32, 512>>>();
    k_out  <<<dim3(NB, NF / 8), 256>>>(Wv, bv, out);
}

// round 3
// speedup vs baseline: 1.1210x; 1.1210x over previous
#include <cuda_runtime.h>
#include <cstddef>

// Problem constants
constexpr int NB = 32;     // batch
constexpr int NS = 2048;   // sequence
constexpr int ND = 512;    // model dim
constexpr int NF = 512;    // dff
constexpr int C1 = 32;     // s-chunks for pass 1
constexpr int C2 = 32;     // s-chunks for pass 2
constexpr int NW = 8;      // warps per pass block (256 threads)
constexpr int UFC = 8;     // f-chunks in k_u
constexpr int FCH = NF / UFC;  // 64 f per chunk
#define INV_SQRT_DFF 0.044194173824159216f  // 1/sqrt(512)

// Scratch (device globals; no allocation anywhere)
__device__ float g_xwp[C1 * NB * ND];   // partial xw per chunk
__device__ float g_xw[NB * ND];
__device__ float g_wsum;
__device__ float g_kwT[NF * NB];        // kw transposed: [f][b]
__device__ float g_cp[64 * NB];         // c partials per f-group of 8
__device__ float g_up[UFC * NB * ND];   // u partials per f-chunk
__device__ float g_u[NB * ND];
__device__ float g_c[NB];
__device__ float g_xtp[C2 * NB * ND];   // partial xt per chunk
__device__ float g_xt[NB * ND];
__device__ float g_Tp[C2 * NB];
__device__ float g_T[NB];

// ---------------------------------------------------------------------------
// Pass 1: xw[b,d] = sum_s Wt[s] * x[b,s,d]   (streams 128 MB of x)
// grid (NB, C1), 256 threads
// ---------------------------------------------------------------------------
__global__ __launch_bounds__(256) void k_xw(const float* __restrict__ x,
                                            const float* __restrict__ Wt) {
    const int b = blockIdx.x, c = blockIdx.y;
    const int tid = threadIdx.x, warp = tid >> 5, lane = tid & 31;
    const int rows = NS / C1;  // 64
    const int s0 = c * rows;

    __shared__ float s_wt[NS / C1];
    __shared__ float4 s4[NW * 128];

    if (tid < rows) s_wt[tid] = Wt[s0 + tid];
    __syncthreads();

    float4 acc[4] = {{0,0,0,0},{0,0,0,0},{0,0,0,0},{0,0,0,0}};
#pragma unroll 2
    for (int r = warp; r < rows; r += NW) {
        const float4* xp = (const float4*)x + ((size_t)b * NS + s0 + r) * (ND / 4);
        const float wt = s_wt[r];
#pragma unroll
        for (int j = 0; j < 4; j++) {
            float4 v = xp[32 * j + lane];
            acc[j].x += wt * v.x; acc[j].y += wt * v.y;
            acc[j].z += wt * v.z; acc[j].w += wt * v.w;
        }
    }
#pragma unroll
    for (int j = 0; j < 4; j++) s4[warp * 128 + 32 * j + lane] = acc[j];
    __syncthreads();

    const float* s = (const float*)s4;
    float v0 = 0.f, v1 = 0.f;
#pragma unroll
    for (int w = 0; w < NW; w++) {
        v0 += s[w * 512 + tid];
        v1 += s[w * 512 + tid + 256];
    }
    float* dst = g_xwp + ((size_t)c * NB + b) * ND;
    dst[tid] = v0;
    dst[tid + 256] = v1;
}

// ---------------------------------------------------------------------------
// Reduce xw partials; block 0 also computes wsum = sum(Wt)
// grid 32, 512 threads
// ---------------------------------------------------------------------------
__global__ __launch_bounds__(512) void k_red1(const float* __restrict__ Wt) {
    const int i = blockIdx.x * 512 + threadIdx.x;
    float v = 0.f;
#pragma unroll
    for (int c = 0; c < C1; c++) v += g_xwp[(size_t)c * NB * ND + i];
    g_xw[i] = v;

    if (blockIdx.x == 0) {
        __shared__ float sr[512];
        float w = 0.f;
        for (int k = threadIdx.x; k < NS; k += 512) w += Wt[k];
        sr[threadIdx.x] = w;
        __syncthreads();
        for (int off = 256; off; off >>= 1) {
            if (threadIdx.x < off) sr[threadIdx.x] += sr[threadIdx.x + off];
            __syncthreads();
        }
        if (threadIdx.x == 0) g_wsum = sr[0];
    }
}

// ---------------------------------------------------------------------------
// kw[b,f] = Wk[f,:].xw[b,:] + bk[f]*wsum   (warp per output, transposed store)
// Also per-block c partial: g_cp[fgroup][b] = sum_{f in group} bq[f]*kw[b,f]
// grid (NB, NF/8), 256 threads
// ---------------------------------------------------------------------------
__global__ __launch_bounds__(256) void k_kw(const float* __restrict__ Wk,
                                            const float* __restrict__ bk,
                                            const float* __restrict__ bq) {
    const int b = blockIdx.x;
    const int warp = threadIdx.x >> 5, lane = threadIdx.x & 31;
    const int f = blockIdx.y * 8 + warp;

    __shared__ float s_c[8];

    const float4* wk = (const float4*)Wk + (size_t)f * (ND / 4);
    const float4* xw = (const float4*)(g_xw + b * ND);
    float dot = 0.f;
#pragma unroll
    for (int q = 0; q < 4; q++) {
        float4 wv = wk[32 * q + lane];
        float4 xv = xw[32 * q + lane];
        dot += wv.x * xv.x + wv.y * xv.y + wv.z * xv.z + wv.w * xv.w;
    }
#pragma unroll
    for (int off = 16; off; off >>= 1) dot += __shfl_xor_sync(0xffffffffu, dot, off);
    if (lane == 0) {
        const float kwv = dot + bk[f] * g_wsum;
        g_kwT[f * NB + b] = kwv;
        s_c[warp] = bq[f] * kwv;
    }
    __syncthreads();
    if (threadIdx.x == 0) {
        float cs = 0.f;
#pragma unroll
        for (int w = 0; w < 8; w++) cs += s_c[w];
        g_cp[blockIdx.y * NB + b] = cs;
    }
}

// ---------------------------------------------------------------------------
// u partial: up[fc][b][d] = sum_{f in chunk} Wq[f,d]*kw[b,f]
// grid (ND/32 = 16 d-tiles, UFC = 8 f-chunks) = 128 blocks, 512 threads.
// Full unroll over 64 f -> high MLP on independent LDG.32; no reg squeeze.
// ---------------------------------------------------------------------------
__global__ void k_u(const float* __restrict__ Wq) {
    const int d0 = blockIdx.x * 32;
    const int fc = blockIdx.y;
    const int f0 = fc * FCH;                 // 64 f per chunk
    const int tid = threadIdx.x;
    const int dl = tid & 31;
    const int bg = tid >> 5;                 // 0..15 (b-pair)

    __shared__ float s_kw[FCH * NB];         // [f_local][b], 8 KB

    // cooperative copy of kw chunk (contiguous in g_kwT): 2048 floats
    ((float4*)s_kw)[tid] = ((const float4*)(g_kwT + (size_t)f0 * NB))[tid];
    __syncthreads();

    float accx = 0.f, accy = 0.f;
    const float* wq = Wq + (size_t)f0 * ND + d0 + dl;
#pragma unroll
    for (int f = 0; f < FCH; f++) {
        const float w = wq[(size_t)f * ND];
        const float2 kv = *(const float2*)&s_kw[f * NB + bg * 2];
        accx += w * kv.x;
        accy += w * kv.y;
    }
    float* dst = g_up + ((size_t)fc * NB + bg * 2) * ND + d0 + dl;
    dst[0]  = accx;
    dst[ND] = accy;
}

// ---------------------------------------------------------------------------
// Reduce u partials -> g_u, c partials -> g_c. grid 32, 512 threads
// ---------------------------------------------------------------------------
__global__ __launch_bounds__(512) void k_ured() {
    const int i = blockIdx.x * 512 + threadIdx.x;
    float v = 0.f;
#pragma unroll
    for (int fc = 0; fc < UFC; fc++) v += g_up[(size_t)fc * NB * ND + i];
    g_u[i] = v;

    if (blockIdx.x == 0 && threadIdx.x < NB) {
        float cs = 0.f;
#pragma unroll
        for (int g = 0; g < 64; g++) cs += g_cp[g * NB + threadIdx.x];
        g_c[threadIdx.x] = cs;
    }
}

// ---------------------------------------------------------------------------
// Pass 2: ta[b,s] = (x[b,s].u[b] + c[b])/sqrt(DFF) + bt
//         xt[b,d] += ta*x[b,s,d] ; T[b] += ta      (streams 128 MB of x)
// grid (NB, C2), 256 threads
// ---------------------------------------------------------------------------
__global__ __launch_bounds__(256) void k_pass2(const float* __restrict__ x,
                                               const float* __restrict__ bt) {
    const int b = blockIdx.x, c = blockIdx.y;
    const int tid = threadIdx.x, warp = tid >> 5, lane = tid & 31;
    const int rows = NS / C2;  // 64
    const int s0 = c * rows;

    __shared__ float4 s4[NW * 128];
    __shared__ float s_T[NW];

    const float4* up = (const float4*)(g_u + b * ND);
    float4 u4[4];
#pragma unroll
    for (int j = 0; j < 4; j++) u4[j] = up[32 * j + lane];
    const float cb = g_c[b];
    const float btv = bt[0];

    float4 acc[4] = {{0,0,0,0},{0,0,0,0},{0,0,0,0},{0,0,0,0}};
    float tsum = 0.f;

#pragma unroll 2
    for (int r = warp; r < rows; r += NW) {
        const float4* xp = (const float4*)x + ((size_t)b * NS + s0 + r) * (ND / 4);
        float4 xv[4];
#pragma unroll
        for (int j = 0; j < 4; j++) xv[j] = xp[32 * j + lane];
        float dot = 0.f;
#pragma unroll
        for (int j = 0; j < 4; j++)
            dot += xv[j].x * u4[j].x + xv[j].y * u4[j].y +
                   xv[j].z * u4[j].z + xv[j].w * u4[j].w;
#pragma unroll
        for (int off = 16; off; off >>= 1) dot += __shfl_xor_sync(0xffffffffu, dot, off);
        const float ta = (dot + cb) * INV_SQRT_DFF + btv;
        tsum += ta;
#pragma unroll
        for (int j = 0; j < 4; j++) {
            acc[j].x += ta * xv[j].x; acc[j].y += ta * xv[j].y;
            acc[j].z += ta * xv[j].z; acc[j].w += ta * xv[j].w;
        }
    }
#pragma unroll
    for (int j = 0; j < 4; j++) s4[warp * 128 + 32 * j + lane] = acc[j];
    if (lane == 0) s_T[warp] = tsum;
    __syncthreads();

    const float* s = (const float*)s4;
    float v0 = 0.f, v1 = 0.f;
#pragma unroll
    for (int w = 0; w < NW; w++) {
        v0 += s[w * 512 + tid];
        v1 += s[w * 512 + tid + 256];
    }
    float* dst = g_xtp + ((size_t)c * NB + b) * ND;
    dst[tid] = v0;
    dst[tid + 256] = v1;
    if (tid == 0) {
        float t = 0.f;
#pragma unroll
        for (int w = 0; w < NW; w++) t += s_T[w];
        g_Tp[c * NB + b] = t;
    }
}

// ---------------------------------------------------------------------------
// Reduce xt partials + T partials. grid 32, 512 threads
// ---------------------------------------------------------------------------
__global__ __launch_bounds__(512) void k_red2() {
    const int i = blockIdx.x * 512 + threadIdx.x;
    float v = 0.f;
#pragma unroll
    for (int c = 0; c < C2; c++) v += g_xtp[(size_t)c * NB * ND + i];
    g_xt[i] = v;

    if (blockIdx.x == 0 && threadIdx.x < NB) {
        float t = 0.f;
#pragma unroll
        for (int c = 0; c < C2; c++) t += g_Tp[c * NB + threadIdx.x];
        g_T[threadIdx.x] = t;
    }
}

// ---------------------------------------------------------------------------
// latent[b,f] = Wv[f,:].xt[b,:] + bv[f]*T[b]    (warp per output)
// grid (NB, NF/8), 256 threads
// ---------------------------------------------------------------------------
__global__ __launch_bounds__(256) void k_out(const float* __restrict__ Wv,
                                             const float* __restrict__ bv,
                                             float* __restrict__ out) {
    const int b = blockIdx.x;
    const int warp = threadIdx.x >> 5, lane = threadIdx.x & 31;
    const int f = blockIdx.y * 8 + warp;

    const float4* wv = (const float4*)Wv + (size_t)f * (ND / 4);
    const float4* xt = (const float4*)(g_xt + b * ND);
    float dot = 0.f;
#pragma unroll
    for (int q = 0; q < 4; q++) {
        float4 w = wv[32 * q + lane];
        float4 v = xt[32 * q + lane];
        dot += w.x * v.x + w.y * v.y + w.z * v.z + w.w * v.w;
    }
#pragma unroll
    for (int off = 16; off; off >>= 1) dot += __shfl_xor_sync(0xffffffffu, dot, off);
    if (lane == 0) out[b * NF + f] = dot + bv[f] * g_T[b];
}

// ---------------------------------------------------------------------------
extern "C" void kernel_launch(void* const* d_in, const int* in_sizes, int n_in,
                              void* d_out, int out_size) {
    const float* x  = (const float*)d_in[0];
    const float* Wq = (const float*)d_in[1];
    const float* bq = (const float*)d_in[2];
    const float* Wk = (const float*)d_in[3];
    const float* bk = (const float*)d_in[4];
    const float* Wv = (const float*)d_in[5];
    const float* bv = (const float*)d_in[6];
    const float* Wt = (const float*)d_in[7];
    const float* bt = (const float*)d_in[8];
    float* out = (float*)d_out;

    k_xw   <<<dim3(NB, C1), 256>>>(x, Wt);
    k_red1 <<<32, 512>>>(Wt);
    k_kw   <<<dim3(NB, NF / 8), 256>>>(Wk, bk, bq);
    k_u    <<<dim3(ND / 32, UFC), 512>>>(Wq);
    k_ured <<<32, 512>>>();
    k_pass2<<<dim3(NB, C2), 256>>>(x, bt);
    k_red2 <<<32, 512>>>();
    k_out  <<<dim3(NB, NF / 8), 256>>>(Wv, bv, out);
}

// round 4
// speedup vs baseline: 1.1500x; 1.0258x over previous
#include <cuda_runtime.h>
#include <cstddef>

// Problem constants
constexpr int NB = 32;     // batch
constexpr int NS = 2048;   // sequence
constexpr int ND = 512;    // model dim
constexpr int NF = 512;    // dff
constexpr int C1 = 32;     // s-chunks for pass 1
constexpr int C2 = 32;     // s-chunks for pass 2
constexpr int NW = 8;      // warps per pass block (256 threads)
constexpr int UFC = 16;    // f-chunks in k_u
constexpr int FCH = NF / UFC;  // 32 f per chunk
#define INV_SQRT_DFF 0.044194173824159216f  // 1/sqrt(512)

// Scratch (device globals; no allocation anywhere)
__device__ float g_xwp[C1 * NB * ND];   // partial xw per chunk
__device__ float g_xw[NB * ND];
__device__ float g_wsum;
__device__ float g_kwT[NF * NB];        // kw transposed: [f][b]
__device__ float g_cp[64 * NB];         // c partials per f-group of 8
__device__ float g_up[UFC * NB * ND];   // u partials per f-chunk
__device__ float g_u[NB * ND];
__device__ float g_c[NB];
__device__ float g_xtp[C2 * NB * ND];   // partial xt per chunk
__device__ float g_xt[NB * ND];
__device__ float g_Tp[C2 * NB];
__device__ float g_T[NB];

// ---------------------------------------------------------------------------
// Pass 1: xw[b,d] = sum_s Wt[s] * x[b,s,d]   (streams 128 MB of x)
// grid (NB, C1), 256 threads
// ---------------------------------------------------------------------------
__global__ __launch_bounds__(256) void k_xw(const float* __restrict__ x,
                                            const float* __restrict__ Wt) {
    const int b = blockIdx.x, c = blockIdx.y;
    const int tid = threadIdx.x, warp = tid >> 5, lane = tid & 31;
    const int rows = NS / C1;  // 64
    const int s0 = c * rows;

    __shared__ float s_wt[NS / C1];
    __shared__ float4 s4[NW * 128];

    if (tid < rows) s_wt[tid] = Wt[s0 + tid];
    __syncthreads();

    float4 acc[4] = {{0,0,0,0},{0,0,0,0},{0,0,0,0},{0,0,0,0}};
#pragma unroll 2
    for (int r = warp; r < rows; r += NW) {
        const float4* xp = (const float4*)x + ((size_t)b * NS + s0 + r) * (ND / 4);
        const float wt = s_wt[r];
#pragma unroll
        for (int j = 0; j < 4; j++) {
            float4 v = xp[32 * j + lane];
            acc[j].x += wt * v.x; acc[j].y += wt * v.y;
            acc[j].z += wt * v.z; acc[j].w += wt * v.w;
        }
    }
#pragma unroll
    for (int j = 0; j < 4; j++) s4[warp * 128 + 32 * j + lane] = acc[j];
    __syncthreads();

    const float* s = (const float*)s4;
    float v0 = 0.f, v1 = 0.f;
#pragma unroll
    for (int w = 0; w < NW; w++) {
        v0 += s[w * 512 + tid];
        v1 += s[w * 512 + tid + 256];
    }
    float* dst = g_xwp + ((size_t)c * NB + b) * ND;
    dst[tid] = v0;
    dst[tid + 256] = v1;
}

// ---------------------------------------------------------------------------
// Reduce xw partials; block 0 also computes wsum = sum(Wt)
// grid 32, 512 threads
// ---------------------------------------------------------------------------
__global__ __launch_bounds__(512) void k_red1(const float* __restrict__ Wt) {
    const int i = blockIdx.x * 512 + threadIdx.x;
    float v = 0.f;
#pragma unroll
    for (int c = 0; c < C1; c++) v += g_xwp[(size_t)c * NB * ND + i];
    g_xw[i] = v;

    if (blockIdx.x == 0) {
        __shared__ float sr[512];
        float w = 0.f;
        for (int k = threadIdx.x; k < NS; k += 512) w += Wt[k];
        sr[threadIdx.x] = w;
        __syncthreads();
        for (int off = 256; off; off >>= 1) {
            if (threadIdx.x < off) sr[threadIdx.x] += sr[threadIdx.x + off];
            __syncthreads();
        }
        if (threadIdx.x == 0) g_wsum = sr[0];
    }
}

// ---------------------------------------------------------------------------
// kw[b,f] = Wk[f,:].xw[b,:] + bk[f]*wsum   (warp per output, transposed store)
// Also per-block c partial: g_cp[fgroup][b] = sum_{f in group} bq[f]*kw[b,f]
// grid (NB, NF/8), 256 threads
// ---------------------------------------------------------------------------
__global__ __launch_bounds__(256) void k_kw(const float* __restrict__ Wk,
                                            const float* __restrict__ bk,
                                            const float* __restrict__ bq) {
    const int b = blockIdx.x;
    const int warp = threadIdx.x >> 5, lane = threadIdx.x & 31;
    const int f = blockIdx.y * 8 + warp;

    __shared__ float s_c[8];

    const float4* wk = (const float4*)Wk + (size_t)f * (ND / 4);
    const float4* xw = (const float4*)(g_xw + b * ND);
    float dot = 0.f;
#pragma unroll
    for (int q = 0; q < 4; q++) {
        float4 wv = wk[32 * q + lane];
        float4 xv = xw[32 * q + lane];
        dot += wv.x * xv.x + wv.y * xv.y + wv.z * xv.z + wv.w * xv.w;
    }
#pragma unroll
    for (int off = 16; off; off >>= 1) dot += __shfl_xor_sync(0xffffffffu, dot, off);
    if (lane == 0) {
        const float kwv = dot + bk[f] * g_wsum;
        g_kwT[f * NB + b] = kwv;
        s_c[warp] = bq[f] * kwv;
    }
    __syncthreads();
    if (threadIdx.x == 0) {
        float cs = 0.f;
#pragma unroll
        for (int w = 0; w < 8; w++) cs += s_c[w];
        g_cp[blockIdx.y * NB + b] = cs;
    }
}

// ---------------------------------------------------------------------------
// u partial: up[fc][b][d] = sum_{f in chunk} Wq[f,d]*kw[b,f]
// grid (ND/32 = 16 d-tiles, UFC = 16 f-chunks) = 256 blocks, 512 threads.
// Explicit register prefetch of all 32 Wq values -> 32 LDGs in flight.
// ---------------------------------------------------------------------------
__global__ __launch_bounds__(512) void k_u(const float* __restrict__ Wq) {
    const int d0 = blockIdx.x * 32;
    const int fc = blockIdx.y;
    const int f0 = fc * FCH;                 // 32 f per chunk
    const int tid = threadIdx.x;
    const int dl = tid & 31;
    const int bg = tid >> 5;                 // 0..15 (b-pair)

    __shared__ float s_kw[FCH * NB];         // [f_local][b], 4 KB

    // cooperative copy of kw chunk (contiguous in g_kwT): 1024 floats
    if (tid < 256)
        ((float4*)s_kw)[tid] = ((const float4*)(g_kwT + (size_t)f0 * NB))[tid];

    // prefetch ALL 32 Wq values into registers (independent LDGs, high MLP)
    const float* wq = Wq + (size_t)f0 * ND + d0 + dl;
    float w[FCH];
#pragma unroll
    for (int f = 0; f < FCH; f++) w[f] = wq[(size_t)f * ND];

    __syncthreads();

    float accx = 0.f, accy = 0.f;
#pragma unroll
    for (int f = 0; f < FCH; f++) {
        const float2 kv = *(const float2*)&s_kw[f * NB + bg * 2];  // warp-uniform broadcast
        accx += w[f] * kv.x;
        accy += w[f] * kv.y;
    }
    float* dst = g_up + ((size_t)fc * NB + bg * 2) * ND + d0 + dl;
    dst[0]  = accx;
    dst[ND] = accy;
}

// ---------------------------------------------------------------------------
// Reduce u partials -> g_u, c partials -> g_c. grid 32, 512 threads
// ---------------------------------------------------------------------------
__global__ __launch_bounds__(512) void k_ured() {
    const int i = blockIdx.x * 512 + threadIdx.x;
    float v = 0.f;
#pragma unroll
    for (int fc = 0; fc < UFC; fc++) v += g_up[(size_t)fc * NB * ND + i];
    g_u[i] = v;

    if (blockIdx.x == 0 && threadIdx.x < NB) {
        float cs = 0.f;
#pragma unroll
        for (int g = 0; g < 64; g++) cs += g_cp[g * NB + threadIdx.x];
        g_c[threadIdx.x] = cs;
    }
}

// ---------------------------------------------------------------------------
// Pass 2: ta[b,s] = (x[b,s].u[b] + c[b])/sqrt(DFF) + bt
//         xt[b,d] += ta*x[b,s,d] ; T[b] += ta      (streams 128 MB of x)
// grid (NB, C2), 256 threads
// ---------------------------------------------------------------------------
__global__ __launch_bounds__(256) void k_pass2(const float* __restrict__ x,
                                               const float* __restrict__ bt) {
    const int b = blockIdx.x, c = blockIdx.y;
    const int tid = threadIdx.x, warp = tid >> 5, lane = tid & 31;
    const int rows = NS / C2;  // 64
    const int s0 = c * rows;

    __shared__ float4 s4[NW * 128];
    __shared__ float s_T[NW];

    const float4* up = (const float4*)(g_u + b * ND);
    float4 u4[4];
#pragma unroll
    for (int j = 0; j < 4; j++) u4[j] = up[32 * j + lane];
    const float cb = g_c[b];
    const float btv = bt[0];

    float4 acc[4] = {{0,0,0,0},{0,0,0,0},{0,0,0,0},{0,0,0,0}};
    float tsum = 0.f;

#pragma unroll 2
    for (int r = warp; r < rows; r += NW) {
        const float4* xp = (const float4*)x + ((size_t)b * NS + s0 + r) * (ND / 4);
        float4 xv[4];
#pragma unroll
        for (int j = 0; j < 4; j++) xv[j] = xp[32 * j + lane];
        float dot = 0.f;
#pragma unroll
        for (int j = 0; j < 4; j++)
            dot += xv[j].x * u4[j].x + xv[j].y * u4[j].y +
                   xv[j].z * u4[j].z + xv[j].w * u4[j].w;
#pragma unroll
        for (int off = 16; off; off >>= 1) dot += __shfl_xor_sync(0xffffffffu, dot, off);
        const float ta = (dot + cb) * INV_SQRT_DFF + btv;
        tsum += ta;
#pragma unroll
        for (int j = 0; j < 4; j++) {
            acc[j].x += ta * xv[j].x; acc[j].y += ta * xv[j].y;
            acc[j].z += ta * xv[j].z; acc[j].w += ta * xv[j].w;
        }
    }
#pragma unroll
    for (int j = 0; j < 4; j++) s4[warp * 128 + 32 * j + lane] = acc[j];
    if (lane == 0) s_T[warp] = tsum;
    __syncthreads();

    const float* s = (const float*)s4;
    float v0 = 0.f, v1 = 0.f;
#pragma unroll
    for (int w = 0; w < NW; w++) {
        v0 += s[w * 512 + tid];
        v1 += s[w * 512 + tid + 256];
    }
    float* dst = g_xtp + ((size_t)c * NB + b) * ND;
    dst[tid] = v0;
    dst[tid + 256] = v1;
    if (tid == 0) {
        float t = 0.f;
#pragma unroll
        for (int w = 0; w < NW; w++) t += s_T[w];
        g_Tp[c * NB + b] = t;
    }
}

// ---------------------------------------------------------------------------
// Reduce xt partials + T partials. grid 32, 512 threads
// ---------------------------------------------------------------------------
__global__ __launch_bounds__(512) void k_red2() {
    const int i = blockIdx.x * 512 + threadIdx.x;
    float v = 0.f;
#pragma unroll
    for (int c = 0; c < C2; c++) v += g_xtp[(size_t)c * NB * ND + i];
    g_xt[i] = v;

    if (blockIdx.x == 0 && threadIdx.x < NB) {
        float t = 0.f;
#pragma unroll
        for (int c = 0; c < C2; c++) t += g_Tp[c * NB + threadIdx.x];
        g_T[threadIdx.x] = t;
    }
}

// ---------------------------------------------------------------------------
// latent[b,f] = Wv[f,:].xt[b,:] + bv[f]*T[b]    (warp per output)
// grid (NB, NF/8), 256 threads
// ---------------------------------------------------------------------------
__global__ __launch_bounds__(256) void k_out(const float* __restrict__ Wv,
                                             const float* __restrict__ bv,
                                             float* __restrict__ out) {
    const int b = blockIdx.x;
    const int warp = threadIdx.x >> 5, lane = threadIdx.x & 31;
    const int f = blockIdx.y * 8 + warp;

    const float4* wv = (const float4*)Wv + (size_t)f * (ND / 4);
    const float4* xt = (const float4*)(g_xt + b * ND);
    float dot = 0.f;
#pragma unroll
    for (int q = 0; q < 4; q++) {
        float4 w = wv[32 * q + lane];
        float4 v = xt[32 * q + lane];
        dot += w.x * v.x + w.y * v.y + w.z * v.z + w.w * v.w;
    }
#pragma unroll
    for (int off = 16; off; off >>= 1) dot += __shfl_xor_sync(0xffffffffu, dot, off);
    if (lane == 0) out[b * NF + f] = dot + bv[f] * g_T[b];
}

// ---------------------------------------------------------------------------
extern "C" void kernel_launch(void* const* d_in, const int* in_sizes, int n_in,
                              void* d_out, int out_size) {
    const float* x  = (const float*)d_in[0];
    const float* Wq = (const float*)d_in[1];
    const float* bq = (const float*)d_in[2];
    const float* Wk = (const float*)d_in[3];
    const float* bk = (const float*)d_in[4];
    const float* Wv = (const float*)d_in[5];
    const float* bv = (const float*)d_in[6];
    const float* Wt = (const float*)d_in[7];
    const float* bt = (const float*)d_in[8];
    float* out = (float*)d_out;

    k_xw   <<<dim3(NB, C1), 256>>>(x, Wt);
    k_red1 <<<32, 512>>>(Wt);
    k_kw   <<<dim3(NB, NF / 8), 256>>>(Wk, bk, bq);
    k_u    <<<dim3(ND / 32, UFC), 512>>>(Wq);
    k_ured <<<32, 512>>>();
    k_pass2<<<dim3(NB, C2), 256>>>(x, bt);
    k_red2 <<<32, 512>>>();
    k_out  <<<dim3(NB, NF / 8), 256>>>(Wv, bv, out);
}

// round 5
// speedup vs baseline: 1.2149x; 1.0564x over previous
#include <cuda_runtime.h>
#include <cstddef>

// Problem constants
constexpr int NB = 32;     // batch
constexpr int NS = 2048;   // sequence
constexpr int ND = 512;    // model dim
constexpr int NF = 512;    // dff
constexpr int CH = 32;     // chunks per batch (blocks per batch)
constexpr int ROWS = NS / CH;  // 64 rows per chunk
constexpr int NW = 8;      // warps per block (256 threads)
#define INV_SQRT_DFF 0.044194173824159216f  // 1/sqrt(512)

// Scratch (device globals; no allocation anywhere)
__device__ float g_xwp[CH * NB * ND];   // xw partials per chunk
__device__ float g_xw[NB * ND];         // reduced xw
__device__ float g_kw[NB * NF];         // kw
__device__ float g_cp[NB * CH];         // c partials (16-f slices)
__device__ float g_u[NB * ND];          // u
__device__ float g_xtp[CH * NB * ND];   // xt partials
__device__ float g_Tp[CH * NB];
__device__ float g_T[NB];
__device__ float g_xt[NB * ND];
__device__ float g_wsum;
__device__ int   g_cnt1[NB], g_cnt2[NB], g_cnt3[NB], g_cnt4[NB];

// ---------------------------------------------------------------------------
// init: zero per-batch counters, compute wsum = sum(Wt). 1 block, 256 thr.
// ---------------------------------------------------------------------------
__global__ __launch_bounds__(256) void k_init(const float* __restrict__ Wt) {
    __shared__ float sr[256];
    const int t = threadIdx.x;
    if (t < NB) { g_cnt1[t] = 0; g_cnt2[t] = 0; g_cnt3[t] = 0; g_cnt4[t] = 0; }
    float w = 0.f;
    for (int k = t; k < NS; k += 256) w += Wt[k];
    sr[t] = w;
    __syncthreads();
    for (int o = 128; o; o >>= 1) {
        if (t < o) sr[t] += sr[t + o];
        __syncthreads();
    }
    if (t == 0) g_wsum = sr[0];
}

// ---------------------------------------------------------------------------
// Fused per-batch pipeline. grid = NB*CH blocks (batch-major), 256 threads.
//   A : xw partial from own x chunk (DRAM stream)
//   B1: reduce xw slice (16 d)      [after cnt1==32]
//   B2: kw slice (16 f) + c partial [after cnt2==32]
//   C : u slice (16 d)              [after cnt3==32]
//   D : pass2 on own x chunk (L1/L2 hit) -> xt/T partials [after cnt4==32]
// Waits are intra-batch only -> deadlock-free at any occupancy.
// ---------------------------------------------------------------------------
__global__ __launch_bounds__(256) void k_fused(
    const float* __restrict__ x,  const float* __restrict__ Wq,
    const float* __restrict__ bq, const float* __restrict__ Wk,
    const float* __restrict__ bk, const float* __restrict__ Wt,
    const float* __restrict__ bt) {
    const int bid = blockIdx.x;
    const int b = bid >> 5;          // batch
    const int c = bid & 31;          // chunk / slice index
    const int tid = threadIdx.x, warp = tid >> 5, lane = tid & 31;
    const int s0 = c * ROWS;

    __shared__ float  s_wt[ROWS];
    __shared__ float4 s4[NW * 128];      // 16 KB reduce buffer (A and D)
    __shared__ float  s_vec[ND];         // xw (B2) / kw (C) broadcast
    __shared__ float  s_red[256];
    __shared__ float  s_kw16[16];
    __shared__ float  s_cp[CH];
    __shared__ float  s_T[NW];

    // ---------------- Stage A: xw partial ----------------
    if (tid < ROWS) s_wt[tid] = Wt[s0 + tid];
    __syncthreads();

    {
        float4 acc[4] = {{0,0,0,0},{0,0,0,0},{0,0,0,0},{0,0,0,0}};
#pragma unroll 2
        for (int r = warp; r < ROWS; r += NW) {
            const float4* xp = (const float4*)x + ((size_t)b * NS + s0 + r) * (ND / 4);
            const float wt = s_wt[r];
#pragma unroll
            for (int j = 0; j < 4; j++) {
                float4 v = xp[32 * j + lane];
                acc[j].x += wt * v.x; acc[j].y += wt * v.y;
                acc[j].z += wt * v.z; acc[j].w += wt * v.w;
            }
        }
#pragma unroll
        for (int j = 0; j < 4; j++) s4[warp * 128 + 32 * j + lane] = acc[j];
        __syncthreads();

        const float* s = (const float*)s4;
        float v0 = 0.f, v1 = 0.f;
#pragma unroll
        for (int w = 0; w < NW; w++) {
            v0 += s[w * 512 + tid];
            v1 += s[w * 512 + tid + 256];
        }
        float* dst = g_xwp + ((size_t)c * NB + b) * ND;
        dst[tid] = v0;
        dst[tid + 256] = v1;
    }
    __threadfence();
    if (tid == 0) {
        atomicAdd(&g_cnt1[b], 1);
        while (((volatile int*)g_cnt1)[b] < CH) __nanosleep(64);
    }
    __syncthreads();

    // ---------------- Stage B1: reduce xw slice (d in [c*16, c*16+16)) -----
    {
        const int dl = tid & 15, g = tid >> 4;      // g: 0..15, 2 chunks each
        float v = 0.f;
#pragma unroll
        for (int k = 0; k < 2; k++) {
            const int ck = g * 2 + k;
            v += __ldcg(&g_xwp[((size_t)ck * NB + b) * ND + c * 16 + dl]);
        }
        s_red[g * 16 + dl] = v;
        __syncthreads();
        if (tid < 16) {
            float xw = 0.f;
#pragma unroll
            for (int g2 = 0; g2 < 16; g2++) xw += s_red[g2 * 16 + tid];
            g_xw[b * ND + c * 16 + tid] = xw;
        }
    }
    __threadfence();
    if (tid == 0) {
        atomicAdd(&g_cnt2[b], 1);
        while (((volatile int*)g_cnt2)[b] < CH) __nanosleep(64);
    }
    __syncthreads();

    // ---------------- Stage B2: kw slice (f in [c*16, c*16+16)) ------------
    {
        s_vec[tid]       = __ldcg(&g_xw[b * ND + tid]);
        s_vec[tid + 256] = __ldcg(&g_xw[b * ND + tid + 256]);
        __syncthreads();

        const float wsum = g_wsum;
#pragma unroll
        for (int j = 0; j < 2; j++) {
            const int f = c * 16 + warp * 2 + j;
            const float* wk = Wk + (size_t)f * ND;
            float acc = 0.f;
#pragma unroll
            for (int i = 0; i < 16; i++)
                acc += wk[lane + 32 * i] * s_vec[lane + 32 * i];
#pragma unroll
            for (int off = 16; off; off >>= 1)
                acc += __shfl_xor_sync(0xffffffffu, acc, off);
            if (lane == 0) {
                const float kwv = acc + bk[f] * wsum;
                g_kw[b * NF + f] = kwv;
                s_kw16[warp * 2 + j] = kwv;
            }
        }
        __syncthreads();
        if (tid == 0) {
            float cp = 0.f;
#pragma unroll
            for (int i = 0; i < 16; i++) cp += bq[c * 16 + i] * s_kw16[i];
            g_cp[b * CH + c] = cp;
        }
    }
    __threadfence();
    if (tid == 0) {
        atomicAdd(&g_cnt3[b], 1);
        while (((volatile int*)g_cnt3)[b] < CH) __nanosleep(64);
    }
    __syncthreads();

    // ---------------- Stage C: u slice (d in [c*16, c*16+16)) --------------
    {
        s_vec[tid]       = __ldcg(&g_kw[b * NF + tid]);
        s_vec[tid + 256] = __ldcg(&g_kw[b * NF + tid + 256]);
        __syncthreads();

        const int dl = tid & 15, fg = tid >> 4;     // fg: 0..15, 32 f each
        float acc = 0.f;
#pragma unroll
        for (int i = 0; i < 32; i++) {
            const int f = fg * 32 + i;
            acc += Wq[(size_t)f * ND + c * 16 + dl] * s_vec[f];
        }
        s_red[fg * 16 + dl] = acc;
        __syncthreads();
        if (tid < 16) {
            float u = 0.f;
#pragma unroll
            for (int g2 = 0; g2 < 16; g2++) u += s_red[g2 * 16 + tid];
            g_u[b * ND + c * 16 + tid] = u;
        }
    }
    __threadfence();
    if (tid == 0) {
        atomicAdd(&g_cnt4[b], 1);
        while (((volatile int*)g_cnt4)[b] < CH) __nanosleep(64);
    }
    __syncthreads();

    // ---------------- Stage D: pass2 on own x chunk (L1/L2-hot) ------------
    {
        if (tid < CH) s_cp[tid] = __ldcg(&g_cp[b * CH + tid]);
        float4 u4[4];
        const float4* up = (const float4*)(g_u + b * ND);
#pragma unroll
        for (int j = 0; j < 4; j++) u4[j] = __ldcg(&up[32 * j + lane]);
        __syncthreads();

        float cb = 0.f;
#pragma unroll
        for (int k = 0; k < CH; k++) cb += s_cp[k];   // same fixed order everywhere
        const float btv = bt[0];

        float4 acc[4] = {{0,0,0,0},{0,0,0,0},{0,0,0,0},{0,0,0,0}};
        float tsum = 0.f;

#pragma unroll 2
        for (int r = warp; r < ROWS; r += NW) {
            const float4* xp = (const float4*)x + ((size_t)b * NS + s0 + r) * (ND / 4);
            float4 xv[4];
#pragma unroll
            for (int j = 0; j < 4; j++) xv[j] = xp[32 * j + lane];
            float dot = 0.f;
#pragma unroll
            for (int j = 0; j < 4; j++)
                dot += xv[j].x * u4[j].x + xv[j].y * u4[j].y +
                       xv[j].z * u4[j].z + xv[j].w * u4[j].w;
#pragma unroll
            for (int off = 16; off; off >>= 1)
                dot += __shfl_xor_sync(0xffffffffu, dot, off);
            const float ta = (dot + cb) * INV_SQRT_DFF + btv;
            tsum += ta;
#pragma unroll
            for (int j = 0; j < 4; j++) {
                acc[j].x += ta * xv[j].x; acc[j].y += ta * xv[j].y;
                acc[j].z += ta * xv[j].z; acc[j].w += ta * xv[j].w;
            }
        }
#pragma unroll
        for (int j = 0; j < 4; j++) s4[warp * 128 + 32 * j + lane] = acc[j];
        if (lane == 0) s_T[warp] = tsum;
        __syncthreads();

        const float* s = (const float*)s4;
        float v0 = 0.f, v1 = 0.f;
#pragma unroll
        for (int w = 0; w < NW; w++) {
            v0 += s[w * 512 + tid];
            v1 += s[w * 512 + tid + 256];
        }
        float* dst = g_xtp + ((size_t)c * NB + b) * ND;
        dst[tid] = v0;
        dst[tid + 256] = v1;
        if (tid == 0) {
            float t = 0.f;
#pragma unroll
            for (int w = 0; w < NW; w++) t += s_T[w];
            g_Tp[c * NB + b] = t;
        }
    }
}

// ---------------------------------------------------------------------------
// Reduce xt partials + T partials. grid 32, 512 threads
// ---------------------------------------------------------------------------
__global__ __launch_bounds__(512) void k_red2() {
    const int i = blockIdx.x * 512 + threadIdx.x;
    float v = 0.f;
#pragma unroll
    for (int c = 0; c < CH; c++) v += g_xtp[(size_t)c * NB * ND + i];
    g_xt[i] = v;

    if (blockIdx.x == 0 && threadIdx.x < NB) {
        float t = 0.f;
#pragma unroll
        for (int c = 0; c < CH; c++) t += g_Tp[c * NB + threadIdx.x];
        g_T[threadIdx.x] = t;
    }
}

// ---------------------------------------------------------------------------
// latent[b,f] = Wv[f,:].xt[b,:] + bv[f]*T[b]    (warp per output)
// grid (NB, NF/8), 256 threads
// ---------------------------------------------------------------------------
__global__ __launch_bounds__(256) void k_out(const float* __restrict__ Wv,
                                             const float* __restrict__ bv,
                                             float* __restrict__ out) {
    const int b = blockIdx.x;
    const int warp = threadIdx.x >> 5, lane = threadIdx.x & 31;
    const int f = blockIdx.y * 8 + warp;

    const float4* wv = (const float4*)Wv + (size_t)f * (ND / 4);
    const float4* xt = (const float4*)(g_xt + b * ND);
    float dot = 0.f;
#pragma unroll
    for (int q = 0; q < 4; q++) {
        float4 w = wv[32 * q + lane];
        float4 v = xt[32 * q + lane];
        dot += w.x * v.x + w.y * v.y + w.z * v.z + w.w * v.w;
    }
#pragma unroll
    for (int off = 16; off; off >>= 1) dot += __shfl_xor_sync(0xffffffffu, dot, off);
    if (lane == 0) out[b * NF + f] = dot + bv[f] * g_T[b];
}

// ---------------------------------------------------------------------------
extern "C" void kernel_launch(void* const* d_in, const int* in_sizes, int n_in,
                              void* d_out, int out_size) {
    const float* x  = (const float*)d_in[0];
    const float* Wq = (const float*)d_in[1];
    const float* bq = (const float*)d_in[2];
    const float* Wk = (const float*)d_in[3];
    const float* bk = (const float*)d_in[4];
    const float* Wv = (const float*)d_in[5];
    const float* bv = (const float*)d_in[6];
    const float* Wt = (const float*)d_in[7];
    const float* bt = (const float*)d_in[8];
    float* out = (float*)d_out;

    k_init <<<1, 256>>>(Wt);
    k_fused<<<NB * CH, 256>>>(x, Wq, bq, Wk, bk, Wt, bt);
    k_red2 <<<32, 512>>>();
    k_out  <<<dim3(NB, NF / 8), 256>>>(Wv, bv, out);
}